// round 1
// baseline (speedup 1.0000x reference)
#include <cuda_runtime.h>
#include <math.h>

#define BB 4
#define SS 4096
#define DD 256
#define ROWS (BB*SS)

// Scratch (device globals — no allocation in kernel_launch)
__device__ float g_q [ROWS*DD];
__device__ float g_k [ROWS*DD];
__device__ float g_v [ROWS*DD];
__device__ float g_ao[ROWS*DD];
__device__ float g_h [ROWS*DD];
__device__ float g_t [ROWS*DD];
__device__ float g_t2[ROWS*DD];

// ---------------------------------------------------------------------------
// GEMM: C[M][256] = A[M][256] @ W[256][256]^T + bias  (W row-major [n][k])
// 64x64 tile per CTA, 256 threads, 4x4 register tile per thread.
// ---------------------------------------------------------------------------
template<bool RELU>
__global__ __launch_bounds__(256) void gemm_k(const float* __restrict__ A,
                                              const float* __restrict__ W,
                                              const float* __restrict__ bias,
                                              float* __restrict__ C) {
    __shared__ float sA[16][65];
    __shared__ float sW[16][65];
    const int tx = threadIdx.x & 15;
    const int ty = threadIdx.x >> 4;
    const int m0 = blockIdx.y * 64;
    const int n0 = blockIdx.x * 64;

    float acc[4][4] = {};

    for (int kc = 0; kc < 256; kc += 16) {
        for (int i = threadIdx.x; i < 64 * 16; i += 256) {
            int m = i >> 4, k = i & 15;
            sA[k][m] = A[(m0 + m) * 256 + kc + k];
            sW[k][m] = W[(n0 + m) * 256 + kc + k];
        }
        __syncthreads();
        #pragma unroll
        for (int k = 0; k < 16; k++) {
            float a[4], b[4];
            #pragma unroll
            for (int i = 0; i < 4; i++) { a[i] = sA[k][ty * 4 + i]; b[i] = sW[k][tx * 4 + i]; }
            #pragma unroll
            for (int i = 0; i < 4; i++)
                #pragma unroll
                for (int j = 0; j < 4; j++)
                    acc[i][j] += a[i] * b[j];
        }
        __syncthreads();
    }

    #pragma unroll
    for (int i = 0; i < 4; i++) {
        #pragma unroll
        for (int j = 0; j < 4; j++) {
            int n = n0 + tx * 4 + j;
            float v = acc[i][j] + bias[n];
            if (RELU) v = fmaxf(v, 0.0f);
            C[(m0 + ty * 4 + i) * 256 + n] = v;
        }
    }
}

// ---------------------------------------------------------------------------
// Flash attention (fp32): per CTA = 64 queries of one batch; stream K/V tiles
// of 64 rows. Online softmax. 256 threads: (tx,ty) in 16x16.
//   scores: thread computes s[4][4] for rows ty*4+i, cols tx*4+j
//   O accum: rows ty*4+i, dims d = dd*64 + tx*4 + c  (acc[4][16])
// SMEM: sQt[256][65] (k-major, prescaled), sKt[256][65], sV[64][256], sP[64][68]
// ---------------------------------------------------------------------------
#define SM_QT 0
#define SM_KT (256*65)
#define SM_V  (2*256*65)
#define SM_P  (2*256*65 + 64*256)
#define SMEM_FLOATS (2*256*65 + 64*256 + 64*68)

__global__ __launch_bounds__(256, 1) void flash_k(const float* __restrict__ Q,
                                                  const float* __restrict__ K,
                                                  const float* __restrict__ V,
                                                  float* __restrict__ O) {
    extern __shared__ float sm[];
    float* sQt = sm + SM_QT;
    float* sKt = sm + SM_KT;
    float* sV  = sm + SM_V;
    float* sP  = sm + SM_P;

    const int b  = blockIdx.y;
    const int q0 = blockIdx.x * 64;
    const float* Qb = Q + ((size_t)b * SS + q0) * DD;
    const float* Kb = K + (size_t)b * SS * DD;
    const float* Vb = V + (size_t)b * SS * DD;

    const int tid = threadIdx.x;
    const int tx = tid & 15;
    const int ty = tid >> 4;

    // Load Q tile transposed (k-major), pre-scaled by 1/sqrt(256)
    for (int i = tid; i < 64 * 256; i += 256) {
        int q = i >> 8, d = i & 255;
        sQt[d * 65 + q] = Qb[q * 256 + d] * 0.0625f;
    }

    float m_i[4], l_i[4];
    float acc[4][16];
    #pragma unroll
    for (int i = 0; i < 4; i++) {
        m_i[i] = -1e30f; l_i[i] = 0.0f;
        #pragma unroll
        for (int d = 0; d < 16; d++) acc[i][d] = 0.0f;
    }
    __syncthreads();

    for (int kt = 0; kt < SS; kt += 64) {
        // Load K tile transposed + V tile row-major
        for (int i = tid; i < 64 * 256; i += 256) {
            int j = i >> 8, d = i & 255;
            float kv = Kb[(kt + j) * 256 + d];
            sKt[d * 65 + j] = kv;
            sV[j * 256 + d] = Vb[(kt + j) * 256 + d];
        }
        __syncthreads();

        // scores s[i][j] = sum_k Q[ty*4+i][k] * K[tx*4+j][k]
        float s[4][4] = {};
        #pragma unroll 4
        for (int k = 0; k < 256; k++) {
            float a[4], c[4];
            #pragma unroll
            for (int i = 0; i < 4; i++) { a[i] = sQt[k * 65 + ty * 4 + i]; c[i] = sKt[k * 65 + tx * 4 + i]; }
            #pragma unroll
            for (int i = 0; i < 4; i++)
                #pragma unroll
                for (int j = 0; j < 4; j++)
                    s[i][j] += a[i] * c[j];
        }

        // online softmax per row (rows replicated across the 16 tx-lanes)
        #pragma unroll
        for (int i = 0; i < 4; i++) {
            float mx = fmaxf(fmaxf(s[i][0], s[i][1]), fmaxf(s[i][2], s[i][3]));
            #pragma unroll
            for (int o = 8; o; o >>= 1) mx = fmaxf(mx, __shfl_xor_sync(0xffffffffu, mx, o));
            float mnew = fmaxf(m_i[i], mx);
            float corr = __expf(m_i[i] - mnew);
            m_i[i] = mnew;
            float p[4], rs = 0.0f;
            #pragma unroll
            for (int j = 0; j < 4; j++) { p[j] = __expf(s[i][j] - mnew); rs += p[j]; }
            #pragma unroll
            for (int o = 8; o; o >>= 1) rs += __shfl_xor_sync(0xffffffffu, rs, o);
            l_i[i] = l_i[i] * corr + rs;
            #pragma unroll
            for (int d = 0; d < 16; d++) acc[i][d] *= corr;
            #pragma unroll
            for (int j = 0; j < 4; j++) sP[(tx * 4 + j) * 68 + ty * 4 + i] = p[j];
        }
        __syncthreads();

        // O += P @ V
        #pragma unroll 4
        for (int j = 0; j < 64; j++) {
            float4 p4 = *(const float4*)(sP + j * 68 + ty * 4);
            float pr[4] = {p4.x, p4.y, p4.z, p4.w};
            #pragma unroll
            for (int dd = 0; dd < 4; dd++) {
                float4 v4 = *(const float4*)(sV + j * 256 + dd * 64 + tx * 4);
                #pragma unroll
                for (int i = 0; i < 4; i++) {
                    acc[i][dd * 4 + 0] += pr[i] * v4.x;
                    acc[i][dd * 4 + 1] += pr[i] * v4.y;
                    acc[i][dd * 4 + 2] += pr[i] * v4.z;
                    acc[i][dd * 4 + 3] += pr[i] * v4.w;
                }
            }
        }
        __syncthreads();
    }

    // normalize + write
    float* Ob = O + ((size_t)b * SS + q0) * DD;
    #pragma unroll
    for (int i = 0; i < 4; i++) {
        float inv = 1.0f / l_i[i];
        #pragma unroll
        for (int dd = 0; dd < 4; dd++) {
            float4 st;
            st.x = acc[i][dd * 4 + 0] * inv;
            st.y = acc[i][dd * 4 + 1] * inv;
            st.z = acc[i][dd * 4 + 2] * inv;
            st.w = acc[i][dd * 4 + 3] * inv;
            *(float4*)(Ob + (ty * 4 + i) * 256 + dd * 64 + tx * 4) = st;
        }
    }
}

// ---------------------------------------------------------------------------
// LayerNorm(X + R) * g + be   — one warp per row of 256
// ---------------------------------------------------------------------------
__global__ __launch_bounds__(256) void ln_k(const float* __restrict__ X,
                                            const float* __restrict__ R,
                                            const float* __restrict__ g,
                                            const float* __restrict__ be,
                                            float* __restrict__ out) {
    int row  = (blockIdx.x * blockDim.x + threadIdx.x) >> 5;
    int lane = threadIdx.x & 31;
    const float* xr = X + (size_t)row * DD;
    const float* rr = R + (size_t)row * DD;

    float v[8];
    float s = 0.0f;
    #pragma unroll
    for (int t = 0; t < 8; t++) {
        int d = t * 32 + lane;
        v[t] = xr[d] + rr[d];
        s += v[t];
    }
    #pragma unroll
    for (int o = 16; o; o >>= 1) s += __shfl_xor_sync(0xffffffffu, s, o);
    float mu = s * (1.0f / 256.0f);

    float var = 0.0f;
    #pragma unroll
    for (int t = 0; t < 8; t++) { float dv = v[t] - mu; var += dv * dv; }
    #pragma unroll
    for (int o = 16; o; o >>= 1) var += __shfl_xor_sync(0xffffffffu, var, o);
    var *= (1.0f / 256.0f);
    float rstd = rsqrtf(var + 1e-5f);

    float* orow = out + (size_t)row * DD;
    #pragma unroll
    for (int t = 0; t < 8; t++) {
        int d = t * 32 + lane;
        orow[d] = (v[t] - mu) * rstd * g[d] + be[d];
    }
}

// ---------------------------------------------------------------------------
extern "C" void kernel_launch(void* const* d_in, const int* in_sizes, int n_in,
                              void* d_out, int out_size) {
    (void)in_sizes; (void)n_in; (void)out_size;
    const float* x  = (const float*)d_in[0];
    const float* Wq = (const float*)d_in[1];
    const float* bq = (const float*)d_in[2];
    const float* Wk = (const float*)d_in[3];
    const float* bk = (const float*)d_in[4];
    const float* Wv = (const float*)d_in[5];
    const float* bv = (const float*)d_in[6];
    const float* Wl = (const float*)d_in[7];
    const float* bl = (const float*)d_in[8];
    const float* g1 = (const float*)d_in[9];
    const float* be1= (const float*)d_in[10];
    const float* g2 = (const float*)d_in[11];
    const float* be2= (const float*)d_in[12];
    float* out = (float*)d_out;

    float *gq, *gk, *gv, *gao, *gh, *gt, *gt2;
    cudaGetSymbolAddress((void**)&gq,  g_q);
    cudaGetSymbolAddress((void**)&gk,  g_k);
    cudaGetSymbolAddress((void**)&gv,  g_v);
    cudaGetSymbolAddress((void**)&gao, g_ao);
    cudaGetSymbolAddress((void**)&gh,  g_h);
    cudaGetSymbolAddress((void**)&gt,  g_t);
    cudaGetSymbolAddress((void**)&gt2, g_t2);

    size_t smem = (size_t)SMEM_FLOATS * sizeof(float);
    cudaFuncSetAttribute(flash_k, cudaFuncAttributeMaxDynamicSharedMemorySize, (int)smem);

    dim3 gemm_grid(DD / 64, ROWS / 64);

    gemm_k<false><<<gemm_grid, 256>>>(x, Wq, bq, gq);
    gemm_k<false><<<gemm_grid, 256>>>(x, Wk, bk, gk);
    gemm_k<false><<<gemm_grid, 256>>>(x, Wv, bv, gv);

    flash_k<<<dim3(SS / 64, BB), 256, smem>>>(gq, gk, gv, gao);

    ln_k<<<ROWS / 8, 256>>>(x, gao, g1, be1, gh);

    gemm_k<true ><<<gemm_grid, 256>>>(gh, Wl, bl, gt);
    gemm_k<false><<<gemm_grid, 256>>>(gt, Wl, bl, gt2);

    ln_k<<<ROWS / 8, 256>>>(x, gt2, g2, be2, out);
}

// round 3
// speedup vs baseline: 3.9795x; 3.9795x over previous
#include <cuda_runtime.h>
#include <cuda_fp16.h>
#include <cstdint>
#include <math.h>

#define BB 4
#define SS 4096
#define DD 256
#define ROWS (BB*SS)

// Scratch (device globals — no allocation in kernel_launch)
__device__ __half g_qh[ROWS*DD];
__device__ __half g_kh[ROWS*DD];
__device__ __half g_vh[ROWS*DD];
__device__ float  g_ao[ROWS*DD];
__device__ float  g_h [ROWS*DD];
__device__ float  g_t [ROWS*DD];
__device__ float  g_t2[ROWS*DD];

// ---------------------------------------------------------------------------
// GEMM: C[M][256] = A[M][256] @ W[256][256]^T + bias  (W row-major [n][k])
// 64x64 tile per CTA, 256 threads, 4x4 register tile per thread.
// HALF_OUT: emit fp16 with scale applied (for QKV feeding the mma flash).
// ---------------------------------------------------------------------------
template<bool RELU, bool HALF_OUT>
__global__ __launch_bounds__(256) void gemm_k(const float* __restrict__ A,
                                              const float* __restrict__ W,
                                              const float* __restrict__ bias,
                                              void* __restrict__ Cv,
                                              float scale) {
    __shared__ float sA[16][65];
    __shared__ float sW[16][65];
    const int tx = threadIdx.x & 15;
    const int ty = threadIdx.x >> 4;
    const int m0 = blockIdx.y * 64;
    const int n0 = blockIdx.x * 64;

    float acc[4][4] = {};

    for (int kc = 0; kc < 256; kc += 16) {
        for (int i = threadIdx.x; i < 64 * 16; i += 256) {
            int m = i >> 4, k = i & 15;
            sA[k][m] = A[(m0 + m) * 256 + kc + k];
            sW[k][m] = W[(n0 + m) * 256 + kc + k];
        }
        __syncthreads();
        #pragma unroll
        for (int k = 0; k < 16; k++) {
            float a[4], b[4];
            #pragma unroll
            for (int i = 0; i < 4; i++) { a[i] = sA[k][ty * 4 + i]; b[i] = sW[k][tx * 4 + i]; }
            #pragma unroll
            for (int i = 0; i < 4; i++)
                #pragma unroll
                for (int j = 0; j < 4; j++)
                    acc[i][j] += a[i] * b[j];
        }
        __syncthreads();
    }

    #pragma unroll
    for (int i = 0; i < 4; i++) {
        #pragma unroll
        for (int j = 0; j < 4; j++) {
            int n = n0 + tx * 4 + j;
            float v = acc[i][j] + bias[n];
            if (RELU) v = fmaxf(v, 0.0f);
            size_t idx = (size_t)(m0 + ty * 4 + i) * 256 + n;
            if (HALF_OUT) ((__half*)Cv)[idx] = __float2half_rn(v * scale);
            else          ((float*)Cv)[idx] = v;
        }
    }
}

// ---------------------------------------------------------------------------
// mma / ldmatrix helpers
// ---------------------------------------------------------------------------
__device__ __forceinline__ uint32_t smem_u32(const void* p) {
    return (uint32_t)__cvta_generic_to_shared(p);
}
__device__ __forceinline__ void ldsm4(uint32_t& r0, uint32_t& r1, uint32_t& r2, uint32_t& r3, uint32_t a) {
    asm volatile("ldmatrix.sync.aligned.m8n8.x4.shared.b16 {%0,%1,%2,%3},[%4];"
                 : "=r"(r0), "=r"(r1), "=r"(r2), "=r"(r3) : "r"(a));
}
__device__ __forceinline__ void ldsm4t(uint32_t& r0, uint32_t& r1, uint32_t& r2, uint32_t& r3, uint32_t a) {
    asm volatile("ldmatrix.sync.aligned.m8n8.x4.trans.shared.b16 {%0,%1,%2,%3},[%4];"
                 : "=r"(r0), "=r"(r1), "=r"(r2), "=r"(r3) : "r"(a));
}
__device__ __forceinline__ void mma16816(float* c, uint32_t a0, uint32_t a1, uint32_t a2, uint32_t a3,
                                         uint32_t b0, uint32_t b1) {
    asm volatile("mma.sync.aligned.m16n8k16.row.col.f32.f16.f16.f32 "
                 "{%0,%1,%2,%3},{%4,%5,%6,%7},{%8,%9},{%0,%1,%2,%3};"
                 : "+f"(c[0]), "+f"(c[1]), "+f"(c[2]), "+f"(c[3])
                 : "r"(a0), "r"(a1), "r"(a2), "r"(a3), "r"(b0), "r"(b1));
}
__device__ __forceinline__ uint32_t packh2(float lo, float hi) {
    __half2 h = __floats2half2_rn(lo, hi);
    return *reinterpret_cast<uint32_t*>(&h);
}

// ---------------------------------------------------------------------------
// Flash attention, fp16 tensor-core. CTA = 128 threads (4 warps), Br=64
// (warp owns m16 strip), Bc=64, D=256. O accumulator fully register-resident.
// SMEM: sQ/sK/sV each [64][264] half (row pad keeps ldmatrix conflict-free).
// Q arrives pre-scaled by 1/sqrt(256) from the QKV GEMM.
// ---------------------------------------------------------------------------
#define LDH 264
#define FLASH_SMEM (3 * 64 * LDH * (int)sizeof(__half))
#define L2E 1.44269504f

__global__ __launch_bounds__(128) void flash_h(const __half* __restrict__ Q,
                                               const __half* __restrict__ K,
                                               const __half* __restrict__ V,
                                               float* __restrict__ O) {
    extern __shared__ __half sm[];
    __half* sQ = sm;
    __half* sK = sm + 64 * LDH;
    __half* sV = sm + 2 * 64 * LDH;

    const int b  = blockIdx.y;
    const int q0 = blockIdx.x * 64;
    const int tid = threadIdx.x;
    const int warp = tid >> 5;
    const int lane = tid & 31;
    const int g  = lane >> 2;   // row group within m16
    const int qd = lane & 3;    // col pair selector

    const __half* Qb = Q + ((size_t)b * SS + q0) * DD;
    const __half* Kb = K + (size_t)b * SS * DD;
    const __half* Vb = V + (size_t)b * SS * DD;

    // Load Q tile (64 x 256 halfs), 16B per thread chunk
    for (int c = tid; c < 2048; c += 128) {
        int r = c >> 5, co = (c & 31) * 8;
        *(uint4*)(sQ + r * LDH + co) = *(const uint4*)(Qb + r * 256 + co);
    }

    float o[32][4];
    #pragma unroll
    for (int t = 0; t < 32; t++) { o[t][0] = 0; o[t][1] = 0; o[t][2] = 0; o[t][3] = 0; }
    float m0 = -1e30f, m1 = -1e30f, l0 = 0.0f, l1 = 0.0f;

    // ldmatrix base addresses (lane-dependent parts)
    const uint32_t aBase = smem_u32(sQ + (warp * 16 + (lane & 15)) * LDH + (lane >> 4) * 8);
    const uint32_t kBase = smem_u32(sK + ((lane & 7) + ((lane >> 4) & 1) * 8) * LDH + ((lane >> 3) & 1) * 8);
    const uint32_t vBase = smem_u32(sV + (lane & 15) * LDH + (lane >> 4) * 8);

    for (int kt = 0; kt < SS; kt += 64) {
        // Load K,V tiles
        for (int c = tid; c < 2048; c += 128) {
            int r = c >> 5, co = (c & 31) * 8;
            *(uint4*)(sK + r * LDH + co) = *(const uint4*)(Kb + (size_t)(kt + r) * 256 + co);
            *(uint4*)(sV + r * LDH + co) = *(const uint4*)(Vb + (size_t)(kt + r) * 256 + co);
        }
        __syncthreads();

        // ---- S = Q K^T : warp computes m16 x n64, accumulate over k=256 ----
        float s[8][4];
        #pragma unroll
        for (int j = 0; j < 8; j++) { s[j][0] = 0; s[j][1] = 0; s[j][2] = 0; s[j][3] = 0; }

        #pragma unroll
        for (int kk = 0; kk < 16; kk++) {
            uint32_t a0, a1, a2, a3;
            ldsm4(a0, a1, a2, a3, aBase + kk * 32);
            #pragma unroll
            for (int jj = 0; jj < 4; jj++) {
                uint32_t k0, k1, k2, k3;
                ldsm4(k0, k1, k2, k3, kBase + jj * 16 * LDH * 2 + kk * 32);
                mma16816(s[2 * jj],     a0, a1, a2, a3, k0, k1);
                mma16816(s[2 * jj + 1], a0, a1, a2, a3, k2, k3);
            }
        }

        // ---- online softmax (rows g and g+8 of this warp's m16 strip) ----
        float rmax0 = -1e30f, rmax1 = -1e30f;
        #pragma unroll
        for (int j = 0; j < 8; j++) {
            rmax0 = fmaxf(rmax0, fmaxf(s[j][0], s[j][1]));
            rmax1 = fmaxf(rmax1, fmaxf(s[j][2], s[j][3]));
        }
        rmax0 = fmaxf(rmax0, __shfl_xor_sync(0xffffffffu, rmax0, 1));
        rmax0 = fmaxf(rmax0, __shfl_xor_sync(0xffffffffu, rmax0, 2));
        rmax1 = fmaxf(rmax1, __shfl_xor_sync(0xffffffffu, rmax1, 1));
        rmax1 = fmaxf(rmax1, __shfl_xor_sync(0xffffffffu, rmax1, 2));

        float mn0 = fmaxf(m0, rmax0), mn1 = fmaxf(m1, rmax1);
        float corr0 = exp2f((m0 - mn0) * L2E);
        float corr1 = exp2f((m1 - mn1) * L2E);
        m0 = mn0; m1 = mn1;

        uint32_t pl[8], ph[8];
        float rs0 = 0.0f, rs1 = 0.0f;
        #pragma unroll
        for (int j = 0; j < 8; j++) {
            float p0 = exp2f((s[j][0] - mn0) * L2E);
            float p1 = exp2f((s[j][1] - mn0) * L2E);
            float p2 = exp2f((s[j][2] - mn1) * L2E);
            float p3 = exp2f((s[j][3] - mn1) * L2E);
            rs0 += p0 + p1; rs1 += p2 + p3;
            pl[j] = packh2(p0, p1);
            ph[j] = packh2(p2, p3);
        }
        rs0 += __shfl_xor_sync(0xffffffffu, rs0, 1);
        rs0 += __shfl_xor_sync(0xffffffffu, rs0, 2);
        rs1 += __shfl_xor_sync(0xffffffffu, rs1, 1);
        rs1 += __shfl_xor_sync(0xffffffffu, rs1, 2);
        l0 = l0 * corr0 + rs0;
        l1 = l1 * corr1 + rs1;

        #pragma unroll
        for (int t = 0; t < 32; t++) {
            o[t][0] *= corr0; o[t][1] *= corr0;
            o[t][2] *= corr1; o[t][3] *= corr1;
        }

        // ---- O += P V : P m16k64 (regs) @ V k64n256 ----
        #pragma unroll
        for (int kk2 = 0; kk2 < 4; kk2++) {
            uint32_t a0 = pl[2 * kk2], a1 = ph[2 * kk2];
            uint32_t a2 = pl[2 * kk2 + 1], a3 = ph[2 * kk2 + 1];
            uint32_t vrow = vBase + kk2 * 16 * LDH * 2;
            #pragma unroll
            for (int nj = 0; nj < 16; nj++) {
                uint32_t v0, v1, v2, v3;
                ldsm4t(v0, v1, v2, v3, vrow + nj * 32);
                mma16816(o[2 * nj],     a0, a1, a2, a3, v0, v1);
                mma16816(o[2 * nj + 1], a0, a1, a2, a3, v2, v3);
            }
        }
        __syncthreads();
    }

    // ---- normalize + store ----
    float inv0 = 1.0f / l0, inv1 = 1.0f / l1;
    float* Ob0 = O + ((size_t)b * SS + q0 + warp * 16 + g) * 256;
    float* Ob1 = Ob0 + 8 * 256;
    #pragma unroll
    for (int j = 0; j < 32; j++) {
        int col = j * 8 + qd * 2;
        float2 w0 = { o[j][0] * inv0, o[j][1] * inv0 };
        float2 w1 = { o[j][2] * inv1, o[j][3] * inv1 };
        *(float2*)(Ob0 + col) = w0;
        *(float2*)(Ob1 + col) = w1;
    }
}

// ---------------------------------------------------------------------------
// LayerNorm(X + R) * g + be   — one warp per row of 256
// ---------------------------------------------------------------------------
__global__ __launch_bounds__(256) void ln_k(const float* __restrict__ X,
                                            const float* __restrict__ R,
                                            const float* __restrict__ g,
                                            const float* __restrict__ be,
                                            float* __restrict__ out) {
    int row  = (blockIdx.x * blockDim.x + threadIdx.x) >> 5;
    int lane = threadIdx.x & 31;
    const float* xr = X + (size_t)row * DD;
    const float* rr = R + (size_t)row * DD;

    float v[8];
    float s = 0.0f;
    #pragma unroll
    for (int t = 0; t < 8; t++) {
        int d = t * 32 + lane;
        v[t] = xr[d] + rr[d];
        s += v[t];
    }
    #pragma unroll
    for (int o = 16; o; o >>= 1) s += __shfl_xor_sync(0xffffffffu, s, o);
    float mu = s * (1.0f / 256.0f);

    float var = 0.0f;
    #pragma unroll
    for (int t = 0; t < 8; t++) { float dv = v[t] - mu; var += dv * dv; }
    #pragma unroll
    for (int o = 16; o; o >>= 1) var += __shfl_xor_sync(0xffffffffu, var, o);
    var *= (1.0f / 256.0f);
    float rstd = rsqrtf(var + 1e-5f);

    float* orow = out + (size_t)row * DD;
    #pragma unroll
    for (int t = 0; t < 8; t++) {
        int d = t * 32 + lane;
        orow[d] = (v[t] - mu) * rstd * g[d] + be[d];
    }
}

// ---------------------------------------------------------------------------
extern "C" void kernel_launch(void* const* d_in, const int* in_sizes, int n_in,
                              void* d_out, int out_size) {
    (void)in_sizes; (void)n_in; (void)out_size;
    const float* x  = (const float*)d_in[0];
    const float* Wq = (const float*)d_in[1];
    const float* bq = (const float*)d_in[2];
    const float* Wk = (const float*)d_in[3];
    const float* bk = (const float*)d_in[4];
    const float* Wv = (const float*)d_in[5];
    const float* bv = (const float*)d_in[6];
    const float* Wl = (const float*)d_in[7];
    const float* bl = (const float*)d_in[8];
    const float* g1 = (const float*)d_in[9];
    const float* be1= (const float*)d_in[10];
    const float* g2 = (const float*)d_in[11];
    const float* be2= (const float*)d_in[12];
    float* out = (float*)d_out;

    __half *gq, *gk, *gv;
    float *gao, *gh, *gt, *gt2;
    cudaGetSymbolAddress((void**)&gq,  g_qh);
    cudaGetSymbolAddress((void**)&gk,  g_kh);
    cudaGetSymbolAddress((void**)&gv,  g_vh);
    cudaGetSymbolAddress((void**)&gao, g_ao);
    cudaGetSymbolAddress((void**)&gh,  g_h);
    cudaGetSymbolAddress((void**)&gt,  g_t);
    cudaGetSymbolAddress((void**)&gt2, g_t2);

    cudaFuncSetAttribute(flash_h, cudaFuncAttributeMaxDynamicSharedMemorySize, FLASH_SMEM);

    dim3 gemm_grid(DD / 64, ROWS / 64);

    // QKV projections -> fp16 (Q pre-scaled by 1/sqrt(256))
    gemm_k<false, true ><<<gemm_grid, 256>>>(x, Wq, bq, gq, 0.0625f);
    gemm_k<false, true ><<<gemm_grid, 256>>>(x, Wk, bk, gk, 1.0f);
    gemm_k<false, true ><<<gemm_grid, 256>>>(x, Wv, bv, gv, 1.0f);

    flash_h<<<dim3(SS / 64, BB), 128, FLASH_SMEM>>>(gq, gk, gv, gao);

    ln_k<<<ROWS / 8, 256>>>(x, gao, g1, be1, gh);

    gemm_k<true,  false><<<gemm_grid, 256>>>(gh, Wl, bl, gt,  1.0f);
    gemm_k<false, false><<<gemm_grid, 256>>>(gt, Wl, bl, gt2, 1.0f);

    ln_k<<<ROWS / 8, 256>>>(x, gt2, g2, be2, out);
}

// round 4
// speedup vs baseline: 8.3050x; 2.0869x over previous
#include <cuda_runtime.h>
#include <cuda_fp16.h>
#include <cstdint>
#include <math.h>

#define BB 4
#define SS 4096
#define DD 256
#define ROWS (BB*SS)

// Scratch (device globals — no allocation in kernel_launch)
__device__ __half g_qh[ROWS*DD];
__device__ __half g_kh[ROWS*DD];
__device__ __half g_vh[ROWS*DD];
__device__ float  g_ao[ROWS*DD];
__device__ __half g_hh[ROWS*DD];
__device__ __half g_th[ROWS*DD];
__device__ float  g_t2[ROWS*DD];

// ---------------------------------------------------------------------------
// mma / ldmatrix helpers
// ---------------------------------------------------------------------------
__device__ __forceinline__ uint32_t smem_u32(const void* p) {
    return (uint32_t)__cvta_generic_to_shared(p);
}
__device__ __forceinline__ void ldsm4(uint32_t& r0, uint32_t& r1, uint32_t& r2, uint32_t& r3, uint32_t a) {
    asm volatile("ldmatrix.sync.aligned.m8n8.x4.shared.b16 {%0,%1,%2,%3},[%4];"
                 : "=r"(r0), "=r"(r1), "=r"(r2), "=r"(r3) : "r"(a));
}
__device__ __forceinline__ void ldsm4t(uint32_t& r0, uint32_t& r1, uint32_t& r2, uint32_t& r3, uint32_t a) {
    asm volatile("ldmatrix.sync.aligned.m8n8.x4.trans.shared.b16 {%0,%1,%2,%3},[%4];"
                 : "=r"(r0), "=r"(r1), "=r"(r2), "=r"(r3) : "r"(a));
}
__device__ __forceinline__ void mma16816(float* c, uint32_t a0, uint32_t a1, uint32_t a2, uint32_t a3,
                                         uint32_t b0, uint32_t b1) {
    asm volatile("mma.sync.aligned.m16n8k16.row.col.f32.f16.f16.f32 "
                 "{%0,%1,%2,%3},{%4,%5,%6,%7},{%8,%9},{%0,%1,%2,%3};"
                 : "+f"(c[0]), "+f"(c[1]), "+f"(c[2]), "+f"(c[3])
                 : "r"(a0), "r"(a1), "r"(a2), "r"(a3), "r"(b0), "r"(b1));
}
__device__ __forceinline__ uint32_t packh2(float lo, float hi) {
    __half2 h = __floats2half2_rn(lo, hi);
    return *reinterpret_cast<uint32_t*>(&h);
}

// ---------------------------------------------------------------------------
// Tensor-core GEMM: C[M][256] = A[M][256] @ W[256][256]^T + bias
// A: fp32 or fp16 row-major (converted to fp16 at smem-store time)
// W: fp32 row-major [n][k] (converted at smem-store time)
// CTA = 256 thr (8 warps), tile 128(m) x 128(n), K chunks of 64.
// Warp tile: m32 x n64 (2 m16 strips x 8 n8 frags).
// ---------------------------------------------------------------------------
#define GLDH 72   // padded smem row length (halfs) for 64-half rows

template<typename TA, bool RELU, bool HALF_OUT>
__global__ __launch_bounds__(256) void hgemm_k(const TA* __restrict__ A,
                                               const float* __restrict__ W,
                                               const float* __restrict__ bias,
                                               void* __restrict__ Cv,
                                               float scale) {
    __shared__ __half sA[128 * GLDH];
    __shared__ __half sW[128 * GLDH];
    const int tid  = threadIdx.x;
    const int warp = tid >> 5, lane = tid & 31;
    const int wm = warp & 3;    // m strip-of-32 index
    const int wn = warp >> 2;   // n half index (0/1)
    const int m0 = blockIdx.y * 128;
    const int n0 = blockIdx.x * 128;

    float acc[2][8][4] = {};

    const uint32_t aAddr = smem_u32(sA + (wm * 32 + (lane & 15)) * GLDH + (lane >> 4) * 8);
    const uint32_t wAddr = smem_u32(sW + (wn * 64 + (lane & 7) + ((lane >> 4) & 1) * 8) * GLDH + ((lane >> 3) & 1) * 8);

    for (int kc = 0; kc < 256; kc += 64) {
        for (int i = tid; i < 1024; i += 256) {
            int r = i >> 3, c8 = (i & 7) * 8;
            // ---- A chunk ----
            if (sizeof(TA) == 2) {
                *(uint4*)(sA + r * GLDH + c8) =
                    *(const uint4*)((const __half*)A + (size_t)(m0 + r) * 256 + kc + c8);
            } else {
                const float* ap = (const float*)A + (size_t)(m0 + r) * 256 + kc + c8;
                float4 f0 = *(const float4*)ap, f1 = *(const float4*)(ap + 4);
                uint4 u;
                u.x = packh2(f0.x, f0.y); u.y = packh2(f0.z, f0.w);
                u.z = packh2(f1.x, f1.y); u.w = packh2(f1.z, f1.w);
                *(uint4*)(sA + r * GLDH + c8) = u;
            }
            // ---- W chunk (always fp32 in gmem) ----
            const float* wp = W + (size_t)(n0 + r) * 256 + kc + c8;
            float4 g0 = *(const float4*)wp, g1 = *(const float4*)(wp + 4);
            uint4 uw;
            uw.x = packh2(g0.x, g0.y); uw.y = packh2(g0.z, g0.w);
            uw.z = packh2(g1.x, g1.y); uw.w = packh2(g1.z, g1.w);
            *(uint4*)(sW + r * GLDH + c8) = uw;
        }
        __syncthreads();

        #pragma unroll
        for (int kk = 0; kk < 4; kk++) {
            uint32_t a[2][4];
            ldsm4(a[0][0], a[0][1], a[0][2], a[0][3], aAddr + kk * 32);
            ldsm4(a[1][0], a[1][1], a[1][2], a[1][3], aAddr + 16 * GLDH * 2 + kk * 32);
            #pragma unroll
            for (int j = 0; j < 4; j++) {
                uint32_t b0, b1, b2, b3;
                ldsm4(b0, b1, b2, b3, wAddr + j * 16 * GLDH * 2 + kk * 32);
                mma16816(acc[0][2 * j],     a[0][0], a[0][1], a[0][2], a[0][3], b0, b1);
                mma16816(acc[0][2 * j + 1], a[0][0], a[0][1], a[0][2], a[0][3], b2, b3);
                mma16816(acc[1][2 * j],     a[1][0], a[1][1], a[1][2], a[1][3], b0, b1);
                mma16816(acc[1][2 * j + 1], a[1][0], a[1][1], a[1][2], a[1][3], b2, b3);
            }
        }
        __syncthreads();
    }

    // ---- epilogue: bias, relu, scale, store ----
    const int g = lane >> 2, qd = lane & 3;
    #pragma unroll
    for (int s = 0; s < 2; s++) {
        int row0 = m0 + wm * 32 + s * 16 + g;
        #pragma unroll
        for (int j = 0; j < 8; j++) {
            int col = n0 + wn * 64 + j * 8 + qd * 2;
            float b0 = bias[col], b1 = bias[col + 1];
            float v00 = acc[s][j][0] + b0, v01 = acc[s][j][1] + b1;
            float v10 = acc[s][j][2] + b0, v11 = acc[s][j][3] + b1;
            if (RELU) {
                v00 = fmaxf(v00, 0.0f); v01 = fmaxf(v01, 0.0f);
                v10 = fmaxf(v10, 0.0f); v11 = fmaxf(v11, 0.0f);
            }
            if (HALF_OUT) {
                *(uint32_t*)((__half*)Cv + (size_t)row0 * 256 + col)      = packh2(v00 * scale, v01 * scale);
                *(uint32_t*)((__half*)Cv + (size_t)(row0 + 8) * 256 + col) = packh2(v10 * scale, v11 * scale);
            } else {
                float2 f0 = {v00, v01}, f1 = {v10, v11};
                *(float2*)((float*)Cv + (size_t)row0 * 256 + col)      = f0;
                *(float2*)((float*)Cv + (size_t)(row0 + 8) * 256 + col) = f1;
            }
        }
    }
}

// ---------------------------------------------------------------------------
// Flash attention, fp16 tensor-core (unchanged from round 3).
// ---------------------------------------------------------------------------
#define LDH 264
#define FLASH_SMEM (3 * 64 * LDH * (int)sizeof(__half))
#define L2E 1.44269504f

__global__ __launch_bounds__(128) void flash_h(const __half* __restrict__ Q,
                                               const __half* __restrict__ K,
                                               const __half* __restrict__ V,
                                               float* __restrict__ O) {
    extern __shared__ __half sm[];
    __half* sQ = sm;
    __half* sK = sm + 64 * LDH;
    __half* sV = sm + 2 * 64 * LDH;

    const int b  = blockIdx.y;
    const int q0 = blockIdx.x * 64;
    const int tid = threadIdx.x;
    const int warp = tid >> 5;
    const int lane = tid & 31;
    const int g  = lane >> 2;
    const int qd = lane & 3;

    const __half* Qb = Q + ((size_t)b * SS + q0) * DD;
    const __half* Kb = K + (size_t)b * SS * DD;
    const __half* Vb = V + (size_t)b * SS * DD;

    for (int c = tid; c < 2048; c += 128) {
        int r = c >> 5, co = (c & 31) * 8;
        *(uint4*)(sQ + r * LDH + co) = *(const uint4*)(Qb + r * 256 + co);
    }

    float o[32][4];
    #pragma unroll
    for (int t = 0; t < 32; t++) { o[t][0] = 0; o[t][1] = 0; o[t][2] = 0; o[t][3] = 0; }
    float m0 = -1e30f, m1 = -1e30f, l0 = 0.0f, l1 = 0.0f;

    const uint32_t aBase = smem_u32(sQ + (warp * 16 + (lane & 15)) * LDH + (lane >> 4) * 8);
    const uint32_t kBase = smem_u32(sK + ((lane & 7) + ((lane >> 4) & 1) * 8) * LDH + ((lane >> 3) & 1) * 8);
    const uint32_t vBase = smem_u32(sV + (lane & 15) * LDH + (lane >> 4) * 8);

    for (int kt = 0; kt < SS; kt += 64) {
        for (int c = tid; c < 2048; c += 128) {
            int r = c >> 5, co = (c & 31) * 8;
            *(uint4*)(sK + r * LDH + co) = *(const uint4*)(Kb + (size_t)(kt + r) * 256 + co);
            *(uint4*)(sV + r * LDH + co) = *(const uint4*)(Vb + (size_t)(kt + r) * 256 + co);
        }
        __syncthreads();

        float s[8][4];
        #pragma unroll
        for (int j = 0; j < 8; j++) { s[j][0] = 0; s[j][1] = 0; s[j][2] = 0; s[j][3] = 0; }

        #pragma unroll
        for (int kk = 0; kk < 16; kk++) {
            uint32_t a0, a1, a2, a3;
            ldsm4(a0, a1, a2, a3, aBase + kk * 32);
            #pragma unroll
            for (int jj = 0; jj < 4; jj++) {
                uint32_t k0, k1, k2, k3;
                ldsm4(k0, k1, k2, k3, kBase + jj * 16 * LDH * 2 + kk * 32);
                mma16816(s[2 * jj],     a0, a1, a2, a3, k0, k1);
                mma16816(s[2 * jj + 1], a0, a1, a2, a3, k2, k3);
            }
        }

        float rmax0 = -1e30f, rmax1 = -1e30f;
        #pragma unroll
        for (int j = 0; j < 8; j++) {
            rmax0 = fmaxf(rmax0, fmaxf(s[j][0], s[j][1]));
            rmax1 = fmaxf(rmax1, fmaxf(s[j][2], s[j][3]));
        }
        rmax0 = fmaxf(rmax0, __shfl_xor_sync(0xffffffffu, rmax0, 1));
        rmax0 = fmaxf(rmax0, __shfl_xor_sync(0xffffffffu, rmax0, 2));
        rmax1 = fmaxf(rmax1, __shfl_xor_sync(0xffffffffu, rmax1, 1));
        rmax1 = fmaxf(rmax1, __shfl_xor_sync(0xffffffffu, rmax1, 2));

        float mn0 = fmaxf(m0, rmax0), mn1 = fmaxf(m1, rmax1);
        float corr0 = exp2f((m0 - mn0) * L2E);
        float corr1 = exp2f((m1 - mn1) * L2E);
        m0 = mn0; m1 = mn1;

        uint32_t pl[8], ph[8];
        float rs0 = 0.0f, rs1 = 0.0f;
        #pragma unroll
        for (int j = 0; j < 8; j++) {
            float p0 = exp2f((s[j][0] - mn0) * L2E);
            float p1 = exp2f((s[j][1] - mn0) * L2E);
            float p2 = exp2f((s[j][2] - mn1) * L2E);
            float p3 = exp2f((s[j][3] - mn1) * L2E);
            rs0 += p0 + p1; rs1 += p2 + p3;
            pl[j] = packh2(p0, p1);
            ph[j] = packh2(p2, p3);
        }
        rs0 += __shfl_xor_sync(0xffffffffu, rs0, 1);
        rs0 += __shfl_xor_sync(0xffffffffu, rs0, 2);
        rs1 += __shfl_xor_sync(0xffffffffu, rs1, 1);
        rs1 += __shfl_xor_sync(0xffffffffu, rs1, 2);
        l0 = l0 * corr0 + rs0;
        l1 = l1 * corr1 + rs1;

        #pragma unroll
        for (int t = 0; t < 32; t++) {
            o[t][0] *= corr0; o[t][1] *= corr0;
            o[t][2] *= corr1; o[t][3] *= corr1;
        }

        #pragma unroll
        for (int kk2 = 0; kk2 < 4; kk2++) {
            uint32_t a0 = pl[2 * kk2], a1 = ph[2 * kk2];
            uint32_t a2 = pl[2 * kk2 + 1], a3 = ph[2 * kk2 + 1];
            uint32_t vrow = vBase + kk2 * 16 * LDH * 2;
            #pragma unroll
            for (int nj = 0; nj < 16; nj++) {
                uint32_t v0, v1, v2, v3;
                ldsm4t(v0, v1, v2, v3, vrow + nj * 32);
                mma16816(o[2 * nj],     a0, a1, a2, a3, v0, v1);
                mma16816(o[2 * nj + 1], a0, a1, a2, a3, v2, v3);
            }
        }
        __syncthreads();
    }

    float inv0 = 1.0f / l0, inv1 = 1.0f / l1;
    float* Ob0 = O + ((size_t)b * SS + q0 + warp * 16 + g) * 256;
    float* Ob1 = Ob0 + 8 * 256;
    #pragma unroll
    for (int j = 0; j < 32; j++) {
        int col = j * 8 + qd * 2;
        float2 w0 = { o[j][0] * inv0, o[j][1] * inv0 };
        float2 w1 = { o[j][2] * inv1, o[j][3] * inv1 };
        *(float2*)(Ob0 + col) = w0;
        *(float2*)(Ob1 + col) = w1;
    }
}

// ---------------------------------------------------------------------------
// LayerNorm(X + R) * g + be — one warp per row; optionally emit fp16
// ---------------------------------------------------------------------------
template<bool HALF_OUT>
__global__ __launch_bounds__(256) void ln_k(const float* __restrict__ X,
                                            const float* __restrict__ R,
                                            const float* __restrict__ g,
                                            const float* __restrict__ be,
                                            void* __restrict__ outv) {
    int row  = (blockIdx.x * blockDim.x + threadIdx.x) >> 5;
    int lane = threadIdx.x & 31;
    const float* xr = X + (size_t)row * DD;
    const float* rr = R + (size_t)row * DD;

    float v[8];
    float s = 0.0f;
    #pragma unroll
    for (int t = 0; t < 8; t++) {
        int d = t * 32 + lane;
        v[t] = xr[d] + rr[d];
        s += v[t];
    }
    #pragma unroll
    for (int o = 16; o; o >>= 1) s += __shfl_xor_sync(0xffffffffu, s, o);
    float mu = s * (1.0f / 256.0f);

    float var = 0.0f;
    #pragma unroll
    for (int t = 0; t < 8; t++) { float dv = v[t] - mu; var += dv * dv; }
    #pragma unroll
    for (int o = 16; o; o >>= 1) var += __shfl_xor_sync(0xffffffffu, var, o);
    var *= (1.0f / 256.0f);
    float rstd = rsqrtf(var + 1e-5f);

    #pragma unroll
    for (int t = 0; t < 8; t++) {
        int d = t * 32 + lane;
        float w = (v[t] - mu) * rstd * g[d] + be[d];
        if (HALF_OUT) ((__half*)outv)[(size_t)row * DD + d] = __float2half_rn(w);
        else          ((float*)outv)[(size_t)row * DD + d] = w;
    }
}

// ---------------------------------------------------------------------------
extern "C" void kernel_launch(void* const* d_in, const int* in_sizes, int n_in,
                              void* d_out, int out_size) {
    (void)in_sizes; (void)n_in; (void)out_size;
    const float* x  = (const float*)d_in[0];
    const float* Wq = (const float*)d_in[1];
    const float* bq = (const float*)d_in[2];
    const float* Wk = (const float*)d_in[3];
    const float* bk = (const float*)d_in[4];
    const float* Wv = (const float*)d_in[5];
    const float* bv = (const float*)d_in[6];
    const float* Wl = (const float*)d_in[7];
    const float* bl = (const float*)d_in[8];
    const float* g1 = (const float*)d_in[9];
    const float* be1= (const float*)d_in[10];
    const float* g2 = (const float*)d_in[11];
    const float* be2= (const float*)d_in[12];
    float* out = (float*)d_out;

    __half *gq, *gk, *gv, *ghh, *gth;
    float *gao, *gt2;
    cudaGetSymbolAddress((void**)&gq,  g_qh);
    cudaGetSymbolAddress((void**)&gk,  g_kh);
    cudaGetSymbolAddress((void**)&gv,  g_vh);
    cudaGetSymbolAddress((void**)&gao, g_ao);
    cudaGetSymbolAddress((void**)&ghh, g_hh);
    cudaGetSymbolAddress((void**)&gth, g_th);
    cudaGetSymbolAddress((void**)&gt2, g_t2);

    cudaFuncSetAttribute(flash_h, cudaFuncAttributeMaxDynamicSharedMemorySize, FLASH_SMEM);

    dim3 ggrid(DD / 128, ROWS / 128);   // (2, 128)

    // QKV projections -> fp16 (Q pre-scaled by 1/sqrt(256))
    hgemm_k<float, false, true ><<<ggrid, 256>>>(x, Wq, bq, gq, 0.0625f);
    hgemm_k<float, false, true ><<<ggrid, 256>>>(x, Wk, bk, gk, 1.0f);
    hgemm_k<float, false, true ><<<ggrid, 256>>>(x, Wv, bv, gv, 1.0f);

    flash_h<<<dim3(SS / 64, BB), 128, FLASH_SMEM>>>(gq, gk, gv, gao);

    ln_k<true ><<<ROWS / 8, 256>>>(x, gao, g1, be1, ghh);

    hgemm_k<__half, true,  true ><<<ggrid, 256>>>(ghh, Wl, bl, gth, 1.0f);
    hgemm_k<__half, false, false><<<ggrid, 256>>>(gth, Wl, bl, gt2, 1.0f);

    ln_k<false><<<ROWS / 8, 256>>>(x, gt2, g2, be2, out);
}

// round 6
// speedup vs baseline: 8.3666x; 1.0074x over previous
#include <cuda_runtime.h>
#include <cuda_fp16.h>
#include <cstdint>
#include <math.h>

#define BB 4
#define SS 4096
#define DD 256
#define ROWS (BB*SS)

// Scratch (device globals — no allocation in kernel_launch)
__device__ __half g_qh[ROWS*DD];
__device__ __half g_kh[ROWS*DD];
__device__ __half g_vh[ROWS*DD];
__device__ float  g_ao[ROWS*DD];
__device__ __half g_hh[ROWS*DD];
__device__ __half g_th[ROWS*DD];
__device__ float  g_t2[ROWS*DD];

// ---------------------------------------------------------------------------
// mma / ldmatrix / cp.async helpers
// ---------------------------------------------------------------------------
__device__ __forceinline__ uint32_t smem_u32(const void* p) {
    return (uint32_t)__cvta_generic_to_shared(p);
}
__device__ __forceinline__ void ldsm4(uint32_t& r0, uint32_t& r1, uint32_t& r2, uint32_t& r3, uint32_t a) {
    asm volatile("ldmatrix.sync.aligned.m8n8.x4.shared.b16 {%0,%1,%2,%3},[%4];"
                 : "=r"(r0), "=r"(r1), "=r"(r2), "=r"(r3) : "r"(a));
}
__device__ __forceinline__ void ldsm4t(uint32_t& r0, uint32_t& r1, uint32_t& r2, uint32_t& r3, uint32_t a) {
    asm volatile("ldmatrix.sync.aligned.m8n8.x4.trans.shared.b16 {%0,%1,%2,%3},[%4];"
                 : "=r"(r0), "=r"(r1), "=r"(r2), "=r"(r3) : "r"(a));
}
__device__ __forceinline__ void mma16816(float* c, uint32_t a0, uint32_t a1, uint32_t a2, uint32_t a3,
                                         uint32_t b0, uint32_t b1) {
    asm volatile("mma.sync.aligned.m16n8k16.row.col.f32.f16.f16.f32 "
                 "{%0,%1,%2,%3},{%4,%5,%6,%7},{%8,%9},{%0,%1,%2,%3};"
                 : "+f"(c[0]), "+f"(c[1]), "+f"(c[2]), "+f"(c[3])
                 : "r"(a0), "r"(a1), "r"(a2), "r"(a3), "r"(b0), "r"(b1));
}
__device__ __forceinline__ uint32_t packh2(float lo, float hi) {
    __half2 h = __floats2half2_rn(lo, hi);
    return *reinterpret_cast<uint32_t*>(&h);
}
__device__ __forceinline__ void cpa16(uint32_t dst, const void* src) {
    asm volatile("cp.async.cg.shared.global [%0], [%1], 16;" :: "r"(dst), "l"(src));
}
__device__ __forceinline__ void cpa_commit() {
    asm volatile("cp.async.commit_group;");
}
template<int N>
__device__ __forceinline__ void cpa_wait() {
    asm volatile("cp.async.wait_group %0;" :: "n"(N));
}

// ---------------------------------------------------------------------------
// Tensor-core GEMM: C[M][256] = A[M][256] @ W[256][256]^T + bias
// ---------------------------------------------------------------------------
#define GLDH 72

template<typename TA, bool RELU, bool HALF_OUT>
__global__ __launch_bounds__(256) void hgemm_k(const TA* __restrict__ A,
                                               const float* __restrict__ W,
                                               const float* __restrict__ bias,
                                               void* __restrict__ Cv,
                                               float scale) {
    __shared__ __half sA[128 * GLDH];
    __shared__ __half sW[128 * GLDH];
    const int tid  = threadIdx.x;
    const int warp = tid >> 5, lane = tid & 31;
    const int wm = warp & 3;
    const int wn = warp >> 2;
    const int m0 = blockIdx.y * 128;
    const int n0 = blockIdx.x * 128;

    float acc[2][8][4] = {};

    const uint32_t aAddr = smem_u32(sA + (wm * 32 + (lane & 15)) * GLDH + (lane >> 4) * 8);
    const uint32_t wAddr = smem_u32(sW + (wn * 64 + (lane & 7) + ((lane >> 4) & 1) * 8) * GLDH + ((lane >> 3) & 1) * 8);

    for (int kc = 0; kc < 256; kc += 64) {
        for (int i = tid; i < 1024; i += 256) {
            int r = i >> 3, c8 = (i & 7) * 8;
            if (sizeof(TA) == 2) {
                *(uint4*)(sA + r * GLDH + c8) =
                    *(const uint4*)((const __half*)A + (size_t)(m0 + r) * 256 + kc + c8);
            } else {
                const float* ap = (const float*)A + (size_t)(m0 + r) * 256 + kc + c8;
                float4 f0 = *(const float4*)ap, f1 = *(const float4*)(ap + 4);
                uint4 u;
                u.x = packh2(f0.x, f0.y); u.y = packh2(f0.z, f0.w);
                u.z = packh2(f1.x, f1.y); u.w = packh2(f1.z, f1.w);
                *(uint4*)(sA + r * GLDH + c8) = u;
            }
            const float* wp = W + (size_t)(n0 + r) * 256 + kc + c8;
            float4 g0 = *(const float4*)wp, g1 = *(const float4*)(wp + 4);
            uint4 uw;
            uw.x = packh2(g0.x, g0.y); uw.y = packh2(g0.z, g0.w);
            uw.z = packh2(g1.x, g1.y); uw.w = packh2(g1.z, g1.w);
            *(uint4*)(sW + r * GLDH + c8) = uw;
        }
        __syncthreads();

        #pragma unroll
        for (int kk = 0; kk < 4; kk++) {
            uint32_t a[2][4];
            ldsm4(a[0][0], a[0][1], a[0][2], a[0][3], aAddr + kk * 32);
            ldsm4(a[1][0], a[1][1], a[1][2], a[1][3], aAddr + 16 * GLDH * 2 + kk * 32);
            #pragma unroll
            for (int j = 0; j < 4; j++) {
                uint32_t b0, b1, b2, b3;
                ldsm4(b0, b1, b2, b3, wAddr + j * 16 * GLDH * 2 + kk * 32);
                mma16816(acc[0][2 * j],     a[0][0], a[0][1], a[0][2], a[0][3], b0, b1);
                mma16816(acc[0][2 * j + 1], a[0][0], a[0][1], a[0][2], a[0][3], b2, b3);
                mma16816(acc[1][2 * j],     a[1][0], a[1][1], a[1][2], a[1][3], b0, b1);
                mma16816(acc[1][2 * j + 1], a[1][0], a[1][1], a[1][2], a[1][3], b2, b3);
            }
        }
        __syncthreads();
    }

    const int g = lane >> 2, qd = lane & 3;
    #pragma unroll
    for (int s = 0; s < 2; s++) {
        int row0 = m0 + wm * 32 + s * 16 + g;
        #pragma unroll
        for (int j = 0; j < 8; j++) {
            int col = n0 + wn * 64 + j * 8 + qd * 2;
            float b0 = bias[col], b1 = bias[col + 1];
            float v00 = acc[s][j][0] + b0, v01 = acc[s][j][1] + b1;
            float v10 = acc[s][j][2] + b0, v11 = acc[s][j][3] + b1;
            if (RELU) {
                v00 = fmaxf(v00, 0.0f); v01 = fmaxf(v01, 0.0f);
                v10 = fmaxf(v10, 0.0f); v11 = fmaxf(v11, 0.0f);
            }
            if (HALF_OUT) {
                *(uint32_t*)((__half*)Cv + (size_t)row0 * 256 + col)      = packh2(v00 * scale, v01 * scale);
                *(uint32_t*)((__half*)Cv + (size_t)(row0 + 8) * 256 + col) = packh2(v10 * scale, v11 * scale);
            } else {
                float2 f0 = {v00, v01}, f1 = {v10, v11};
                *(float2*)((float*)Cv + (size_t)row0 * 256 + col)      = f0;
                *(float2*)((float*)Cv + (size_t)(row0 + 8) * 256 + col) = f1;
            }
        }
    }
}

// ---------------------------------------------------------------------------
// Flash attention, fp16 tensor-core, cp.async double-buffered K/V.
// CTA = 128 thr (4 warps), Br=64, Bc=64, D=256. O register-resident.
// SMEM: Q[64][264] + 2 stages of (K[64][264], V[64][264]) = 165 KB.
// ---------------------------------------------------------------------------
#define LDH 264
#define TILEH (64 * LDH)                 // halfs per tile buffer
#define STGH  (2 * TILEH)                // halfs per stage (K+V)
#define FLASH_SMEM ((TILEH + 2 * STGH) * (int)sizeof(__half))
#define L2E 1.44269504f

__global__ __launch_bounds__(128) void flash_h(const __half* __restrict__ Q,
                                               const __half* __restrict__ K,
                                               const __half* __restrict__ V,
                                               float* __restrict__ O) {
    extern __shared__ __half sm[];
    __half* sQ  = sm;
    __half* sK0 = sm + TILEH;            // stage s: K at sK0 + s*STGH, V at +TILEH
    __half* sV0 = sK0 + TILEH;

    const int b  = blockIdx.y;
    const int q0 = blockIdx.x * 64;
    const int tid = threadIdx.x;
    const int warp = tid >> 5;
    const int lane = tid & 31;
    const int g  = lane >> 2;
    const int qd = lane & 3;

    const __half* Qb = Q + ((size_t)b * SS + q0) * DD;
    const __half* Kb = K + (size_t)b * SS * DD;
    const __half* Vb = V + (size_t)b * SS * DD;

    // Load Q tile (64 x 256 halfs) via cp.async (merged into group 0)
    for (int c = tid; c < 2048; c += 128) {
        int r = c >> 5, co = (c & 31) * 8;
        cpa16(smem_u32(sQ + r * LDH + co), Qb + r * 256 + co);
    }

    // prologue: stage 0 <- tile 0
    {
        const uint32_t kDst = smem_u32(sK0);
        for (int c = tid; c < 2048; c += 128) {
            int r = c >> 5, co = (c & 31) * 8;
            cpa16(kDst + (r * LDH + co) * 2,             Kb + (size_t)r * 256 + co);
            cpa16(kDst + (TILEH + r * LDH + co) * 2,     Vb + (size_t)r * 256 + co);
        }
        cpa_commit();
    }

    float o[32][4];
    #pragma unroll
    for (int t = 0; t < 32; t++) { o[t][0] = 0; o[t][1] = 0; o[t][2] = 0; o[t][3] = 0; }
    float m0 = -1e30f, m1 = -1e30f, l0 = 0.0f, l1 = 0.0f;

    const uint32_t aBase  = smem_u32(sQ + (warp * 16 + (lane & 15)) * LDH + (lane >> 4) * 8);
    // K (B-operand, non-trans ldsm) lane mapping
    const uint32_t kBase0 = smem_u32(sK0 + ((lane & 7) + ((lane >> 4) & 1) * 8) * LDH + ((lane >> 3) & 1) * 8);
    // V (trans ldsm) lane mapping — distinct from K's! (round-5 bug was here)
    const uint32_t vBase0 = smem_u32(sV0 + (lane & 15) * LDH + (lane >> 4) * 8);
    const uint32_t kDst0  = smem_u32(sK0);

    for (int ti = 0; ti < SS / 64; ti++) {
        // issue next tile into the other stage
        if (ti + 1 < SS / 64) {
            const uint32_t kDst = kDst0 + ((ti + 1) & 1) * STGH * 2;
            const __half* Kn = Kb + (size_t)(ti + 1) * 64 * 256;
            const __half* Vn = Vb + (size_t)(ti + 1) * 64 * 256;
            for (int c = tid; c < 2048; c += 128) {
                int r = c >> 5, co = (c & 31) * 8;
                cpa16(kDst + (r * LDH + co) * 2,         Kn + (size_t)r * 256 + co);
                cpa16(kDst + (TILEH + r * LDH + co) * 2, Vn + (size_t)r * 256 + co);
            }
        }
        cpa_commit();
        cpa_wait<1>();          // current tile (and Q on ti==0) resident
        __syncthreads();

        const uint32_t kBase = kBase0 + (ti & 1) * STGH * 2;
        const uint32_t vBase = vBase0 + (ti & 1) * STGH * 2;

        // ---- S = Q K^T ----
        float s[8][4];
        #pragma unroll
        for (int j = 0; j < 8; j++) { s[j][0] = 0; s[j][1] = 0; s[j][2] = 0; s[j][3] = 0; }

        #pragma unroll
        for (int kk = 0; kk < 16; kk++) {
            uint32_t a0, a1, a2, a3;
            ldsm4(a0, a1, a2, a3, aBase + kk * 32);
            #pragma unroll
            for (int jj = 0; jj < 4; jj++) {
                uint32_t k0, k1, k2, k3;
                ldsm4(k0, k1, k2, k3, kBase + jj * 16 * LDH * 2 + kk * 32);
                mma16816(s[2 * jj],     a0, a1, a2, a3, k0, k1);
                mma16816(s[2 * jj + 1], a0, a1, a2, a3, k2, k3);
            }
        }

        // ---- online softmax ----
        float rmax0 = -1e30f, rmax1 = -1e30f;
        #pragma unroll
        for (int j = 0; j < 8; j++) {
            rmax0 = fmaxf(rmax0, fmaxf(s[j][0], s[j][1]));
            rmax1 = fmaxf(rmax1, fmaxf(s[j][2], s[j][3]));
        }
        rmax0 = fmaxf(rmax0, __shfl_xor_sync(0xffffffffu, rmax0, 1));
        rmax0 = fmaxf(rmax0, __shfl_xor_sync(0xffffffffu, rmax0, 2));
        rmax1 = fmaxf(rmax1, __shfl_xor_sync(0xffffffffu, rmax1, 1));
        rmax1 = fmaxf(rmax1, __shfl_xor_sync(0xffffffffu, rmax1, 2));

        float mn0 = fmaxf(m0, rmax0), mn1 = fmaxf(m1, rmax1);
        float corr0 = exp2f((m0 - mn0) * L2E);
        float corr1 = exp2f((m1 - mn1) * L2E);
        m0 = mn0; m1 = mn1;

        uint32_t pl[8], ph[8];
        float rs0 = 0.0f, rs1 = 0.0f;
        #pragma unroll
        for (int j = 0; j < 8; j++) {
            float p0 = exp2f((s[j][0] - mn0) * L2E);
            float p1 = exp2f((s[j][1] - mn0) * L2E);
            float p2 = exp2f((s[j][2] - mn1) * L2E);
            float p3 = exp2f((s[j][3] - mn1) * L2E);
            rs0 += p0 + p1; rs1 += p2 + p3;
            pl[j] = packh2(p0, p1);
            ph[j] = packh2(p2, p3);
        }
        rs0 += __shfl_xor_sync(0xffffffffu, rs0, 1);
        rs0 += __shfl_xor_sync(0xffffffffu, rs0, 2);
        rs1 += __shfl_xor_sync(0xffffffffu, rs1, 1);
        rs1 += __shfl_xor_sync(0xffffffffu, rs1, 2);
        l0 = l0 * corr0 + rs0;
        l1 = l1 * corr1 + rs1;

        #pragma unroll
        for (int t = 0; t < 32; t++) {
            o[t][0] *= corr0; o[t][1] *= corr0;
            o[t][2] *= corr1; o[t][3] *= corr1;
        }

        // ---- O += P V ----
        #pragma unroll
        for (int kk2 = 0; kk2 < 4; kk2++) {
            uint32_t a0 = pl[2 * kk2], a1 = ph[2 * kk2];
            uint32_t a2 = pl[2 * kk2 + 1], a3 = ph[2 * kk2 + 1];
            uint32_t vrow = vBase + kk2 * 16 * LDH * 2;
            #pragma unroll
            for (int nj = 0; nj < 16; nj++) {
                uint32_t v0, v1, v2, v3;
                ldsm4t(v0, v1, v2, v3, vrow + nj * 32);
                mma16816(o[2 * nj],     a0, a1, a2, a3, v0, v1);
                mma16816(o[2 * nj + 1], a0, a1, a2, a3, v2, v3);
            }
        }
        __syncthreads();   // free this stage for the prefetch issued next iteration
    }

    // ---- normalize + store ----
    float inv0 = 1.0f / l0, inv1 = 1.0f / l1;
    float* Ob0 = O + ((size_t)b * SS + q0 + warp * 16 + g) * 256;
    float* Ob1 = Ob0 + 8 * 256;
    #pragma unroll
    for (int j = 0; j < 32; j++) {
        int col = j * 8 + qd * 2;
        float2 w0 = { o[j][0] * inv0, o[j][1] * inv0 };
        float2 w1 = { o[j][2] * inv1, o[j][3] * inv1 };
        *(float2*)(Ob0 + col) = w0;
        *(float2*)(Ob1 + col) = w1;
    }
}

// ---------------------------------------------------------------------------
// LayerNorm(X + R) * g + be — one warp per row; optionally emit fp16
// ---------------------------------------------------------------------------
template<bool HALF_OUT>
__global__ __launch_bounds__(256) void ln_k(const float* __restrict__ X,
                                            const float* __restrict__ R,
                                            const float* __restrict__ g,
                                            const float* __restrict__ be,
                                            void* __restrict__ outv) {
    int row  = (blockIdx.x * blockDim.x + threadIdx.x) >> 5;
    int lane = threadIdx.x & 31;
    const float* xr = X + (size_t)row * DD;
    const float* rr = R + (size_t)row * DD;

    float v[8];
    float s = 0.0f;
    #pragma unroll
    for (int t = 0; t < 8; t++) {
        int d = t * 32 + lane;
        v[t] = xr[d] + rr[d];
        s += v[t];
    }
    #pragma unroll
    for (int o = 16; o; o >>= 1) s += __shfl_xor_sync(0xffffffffu, s, o);
    float mu = s * (1.0f / 256.0f);

    float var = 0.0f;
    #pragma unroll
    for (int t = 0; t < 8; t++) { float dv = v[t] - mu; var += dv * dv; }
    #pragma unroll
    for (int o = 16; o; o >>= 1) var += __shfl_xor_sync(0xffffffffu, var, o);
    var *= (1.0f / 256.0f);
    float rstd = rsqrtf(var + 1e-5f);

    #pragma unroll
    for (int t = 0; t < 8; t++) {
        int d = t * 32 + lane;
        float w = (v[t] - mu) * rstd * g[d] + be[d];
        if (HALF_OUT) ((__half*)outv)[(size_t)row * DD + d] = __float2half_rn(w);
        else          ((float*)outv)[(size_t)row * DD + d] = w;
    }
}

// ---------------------------------------------------------------------------
extern "C" void kernel_launch(void* const* d_in, const int* in_sizes, int n_in,
                              void* d_out, int out_size) {
    (void)in_sizes; (void)n_in; (void)out_size;
    const float* x  = (const float*)d_in[0];
    const float* Wq = (const float*)d_in[1];
    const float* bq = (const float*)d_in[2];
    const float* Wk = (const float*)d_in[3];
    const float* bk = (const float*)d_in[4];
    const float* Wv = (const float*)d_in[5];
    const float* bv = (const float*)d_in[6];
    const float* Wl = (const float*)d_in[7];
    const float* bl = (const float*)d_in[8];
    const float* g1 = (const float*)d_in[9];
    const float* be1= (const float*)d_in[10];
    const float* g2 = (const float*)d_in[11];
    const float* be2= (const float*)d_in[12];
    float* out = (float*)d_out;

    __half *gq, *gk, *gv, *ghh, *gth;
    float *gao, *gt2;
    cudaGetSymbolAddress((void**)&gq,  g_qh);
    cudaGetSymbolAddress((void**)&gk,  g_kh);
    cudaGetSymbolAddress((void**)&gv,  g_vh);
    cudaGetSymbolAddress((void**)&gao, g_ao);
    cudaGetSymbolAddress((void**)&ghh, g_hh);
    cudaGetSymbolAddress((void**)&gth, g_th);
    cudaGetSymbolAddress((void**)&gt2, g_t2);

    cudaFuncSetAttribute(flash_h, cudaFuncAttributeMaxDynamicSharedMemorySize, FLASH_SMEM);

    dim3 ggrid(DD / 128, ROWS / 128);   // (2, 128)

    hgemm_k<float, false, true ><<<ggrid, 256>>>(x, Wq, bq, gq, 0.0625f);
    hgemm_k<float, false, true ><<<ggrid, 256>>>(x, Wk, bk, gk, 1.0f);
    hgemm_k<float, false, true ><<<ggrid, 256>>>(x, Wv, bv, gv, 1.0f);

    flash_h<<<dim3(SS / 64, BB), 128, FLASH_SMEM>>>(gq, gk, gv, gao);

    ln_k<true ><<<ROWS / 8, 256>>>(x, gao, g1, be1, ghh);

    hgemm_k<__half, true,  true ><<<ggrid, 256>>>(ghh, Wl, bl, gth, 1.0f);
    hgemm_k<__half, false, false><<<ggrid, 256>>>(gth, Wl, bl, gt2, 1.0f);

    ln_k<false><<<ROWS / 8, 256>>>(x, gt2, g2, be2, out);
}

// round 7
// speedup vs baseline: 9.7549x; 1.1659x over previous
#include <cuda_runtime.h>
#include <cuda_fp16.h>
#include <cstdint>
#include <math.h>

#define BB 4
#define SS 4096
#define DD 256
#define ROWS (BB*SS)

// Scratch (device globals — no allocation in kernel_launch)
__device__ __half g_qh[ROWS*DD];
__device__ __half g_kh[ROWS*DD];
__device__ __half g_vh[ROWS*DD];
__device__ float  g_ao[ROWS*DD];
__device__ __half g_hh[ROWS*DD];
__device__ __half g_th[ROWS*DD];
__device__ float  g_t2[ROWS*DD];

// ---------------------------------------------------------------------------
// mma / ldmatrix / cp.async helpers
// ---------------------------------------------------------------------------
__device__ __forceinline__ uint32_t smem_u32(const void* p) {
    return (uint32_t)__cvta_generic_to_shared(p);
}
__device__ __forceinline__ void ldsm4(uint32_t& r0, uint32_t& r1, uint32_t& r2, uint32_t& r3, uint32_t a) {
    asm volatile("ldmatrix.sync.aligned.m8n8.x4.shared.b16 {%0,%1,%2,%3},[%4];"
                 : "=r"(r0), "=r"(r1), "=r"(r2), "=r"(r3) : "r"(a));
}
__device__ __forceinline__ void ldsm4t(uint32_t& r0, uint32_t& r1, uint32_t& r2, uint32_t& r3, uint32_t a) {
    asm volatile("ldmatrix.sync.aligned.m8n8.x4.trans.shared.b16 {%0,%1,%2,%3},[%4];"
                 : "=r"(r0), "=r"(r1), "=r"(r2), "=r"(r3) : "r"(a));
}
__device__ __forceinline__ void mma16816(float* c, uint32_t a0, uint32_t a1, uint32_t a2, uint32_t a3,
                                         uint32_t b0, uint32_t b1) {
    asm volatile("mma.sync.aligned.m16n8k16.row.col.f32.f16.f16.f32 "
                 "{%0,%1,%2,%3},{%4,%5,%6,%7},{%8,%9},{%0,%1,%2,%3};"
                 : "+f"(c[0]), "+f"(c[1]), "+f"(c[2]), "+f"(c[3])
                 : "r"(a0), "r"(a1), "r"(a2), "r"(a3), "r"(b0), "r"(b1));
}
__device__ __forceinline__ uint32_t packh2(float lo, float hi) {
    __half2 h = __floats2half2_rn(lo, hi);
    return *reinterpret_cast<uint32_t*>(&h);
}
__device__ __forceinline__ void cpa16(uint32_t dst, const void* src) {
    asm volatile("cp.async.cg.shared.global [%0], [%1], 16;" :: "r"(dst), "l"(src));
}
__device__ __forceinline__ void cpa_commit() {
    asm volatile("cp.async.commit_group;");
}
template<int N>
__device__ __forceinline__ void cpa_wait() {
    asm volatile("cp.async.wait_group %0;" :: "n"(N));
}

// ---------------------------------------------------------------------------
// Tensor-core GEMM: C[M][256] = A[M][256] @ W[256][256]^T + bias (unchanged)
// ---------------------------------------------------------------------------
#define GLDH 72

template<typename TA, bool RELU, bool HALF_OUT>
__global__ __launch_bounds__(256) void hgemm_k(const TA* __restrict__ A,
                                               const float* __restrict__ W,
                                               const float* __restrict__ bias,
                                               void* __restrict__ Cv,
                                               float scale) {
    __shared__ __half sA[128 * GLDH];
    __shared__ __half sW[128 * GLDH];
    const int tid  = threadIdx.x;
    const int warp = tid >> 5, lane = tid & 31;
    const int wm = warp & 3;
    const int wn = warp >> 2;
    const int m0 = blockIdx.y * 128;
    const int n0 = blockIdx.x * 128;

    float acc[2][8][4] = {};

    const uint32_t aAddr = smem_u32(sA + (wm * 32 + (lane & 15)) * GLDH + (lane >> 4) * 8);
    const uint32_t wAddr = smem_u32(sW + (wn * 64 + (lane & 7) + ((lane >> 4) & 1) * 8) * GLDH + ((lane >> 3) & 1) * 8);

    for (int kc = 0; kc < 256; kc += 64) {
        for (int i = tid; i < 1024; i += 256) {
            int r = i >> 3, c8 = (i & 7) * 8;
            if (sizeof(TA) == 2) {
                *(uint4*)(sA + r * GLDH + c8) =
                    *(const uint4*)((const __half*)A + (size_t)(m0 + r) * 256 + kc + c8);
            } else {
                const float* ap = (const float*)A + (size_t)(m0 + r) * 256 + kc + c8;
                float4 f0 = *(const float4*)ap, f1 = *(const float4*)(ap + 4);
                uint4 u;
                u.x = packh2(f0.x, f0.y); u.y = packh2(f0.z, f0.w);
                u.z = packh2(f1.x, f1.y); u.w = packh2(f1.z, f1.w);
                *(uint4*)(sA + r * GLDH + c8) = u;
            }
            const float* wp = W + (size_t)(n0 + r) * 256 + kc + c8;
            float4 g0 = *(const float4*)wp, g1 = *(const float4*)(wp + 4);
            uint4 uw;
            uw.x = packh2(g0.x, g0.y); uw.y = packh2(g0.z, g0.w);
            uw.z = packh2(g1.x, g1.y); uw.w = packh2(g1.z, g1.w);
            *(uint4*)(sW + r * GLDH + c8) = uw;
        }
        __syncthreads();

        #pragma unroll
        for (int kk = 0; kk < 4; kk++) {
            uint32_t a[2][4];
            ldsm4(a[0][0], a[0][1], a[0][2], a[0][3], aAddr + kk * 32);
            ldsm4(a[1][0], a[1][1], a[1][2], a[1][3], aAddr + 16 * GLDH * 2 + kk * 32);
            #pragma unroll
            for (int j = 0; j < 4; j++) {
                uint32_t b0, b1, b2, b3;
                ldsm4(b0, b1, b2, b3, wAddr + j * 16 * GLDH * 2 + kk * 32);
                mma16816(acc[0][2 * j],     a[0][0], a[0][1], a[0][2], a[0][3], b0, b1);
                mma16816(acc[0][2 * j + 1], a[0][0], a[0][1], a[0][2], a[0][3], b2, b3);
                mma16816(acc[1][2 * j],     a[1][0], a[1][1], a[1][2], a[1][3], b0, b1);
                mma16816(acc[1][2 * j + 1], a[1][0], a[1][1], a[1][2], a[1][3], b2, b3);
            }
        }
        __syncthreads();
    }

    const int g = lane >> 2, qd = lane & 3;
    #pragma unroll
    for (int s = 0; s < 2; s++) {
        int row0 = m0 + wm * 32 + s * 16 + g;
        #pragma unroll
        for (int j = 0; j < 8; j++) {
            int col = n0 + wn * 64 + j * 8 + qd * 2;
            float b0 = bias[col], b1 = bias[col + 1];
            float v00 = acc[s][j][0] + b0, v01 = acc[s][j][1] + b1;
            float v10 = acc[s][j][2] + b0, v11 = acc[s][j][3] + b1;
            if (RELU) {
                v00 = fmaxf(v00, 0.0f); v01 = fmaxf(v01, 0.0f);
                v10 = fmaxf(v10, 0.0f); v11 = fmaxf(v11, 0.0f);
            }
            if (HALF_OUT) {
                *(uint32_t*)((__half*)Cv + (size_t)row0 * 256 + col)      = packh2(v00 * scale, v01 * scale);
                *(uint32_t*)((__half*)Cv + (size_t)(row0 + 8) * 256 + col) = packh2(v10 * scale, v11 * scale);
            } else {
                float2 f0 = {v00, v01}, f1 = {v10, v11};
                *(float2*)((float*)Cv + (size_t)row0 * 256 + col)      = f0;
                *(float2*)((float*)Cv + (size_t)(row0 + 8) * 256 + col) = f1;
            }
        }
    }
}

// ---------------------------------------------------------------------------
// Flash attention, fp16 tensor-core, cp.async double-buffered K/V.
// Round 7: Br=128 (8 warps, 256 threads), Bc=64, grid = 32x4 = 128 CTAs
// -> exactly one wave on 148 SMs, 2 warps/SMSP for latency hiding.
// SMEM: Q[128][264] + 2 stages of (K[64][264], V[64][264]) = 198 KB.
// ---------------------------------------------------------------------------
#define LDH 264
#define BRQ 128
#define QTILEH (BRQ * LDH)
#define TILEH (64 * LDH)                 // halfs per K or V tile buffer
#define STGH  (2 * TILEH)                // halfs per stage (K+V)
#define FLASH_SMEM ((QTILEH + 2 * STGH) * (int)sizeof(__half))
#define L2E 1.44269504f

__global__ __launch_bounds__(256, 1) void flash_h(const __half* __restrict__ Q,
                                                  const __half* __restrict__ K,
                                                  const __half* __restrict__ V,
                                                  float* __restrict__ O) {
    extern __shared__ __half sm[];
    __half* sQ  = sm;
    __half* sK0 = sm + QTILEH;           // stage s: K at sK0 + s*STGH, V at +TILEH
    __half* sV0 = sK0 + TILEH;

    const int b  = blockIdx.y;
    const int q0 = blockIdx.x * BRQ;
    const int tid = threadIdx.x;
    const int warp = tid >> 5;
    const int lane = tid & 31;
    const int g  = lane >> 2;
    const int qd = lane & 3;

    const __half* Qb = Q + ((size_t)b * SS + q0) * DD;
    const __half* Kb = K + (size_t)b * SS * DD;
    const __half* Vb = V + (size_t)b * SS * DD;

    // Load Q tile (128 x 256 halfs) via cp.async (merged into group 0)
    for (int c = tid; c < 4096; c += 256) {
        int r = c >> 5, co = (c & 31) * 8;
        cpa16(smem_u32(sQ + r * LDH + co), Qb + (size_t)r * 256 + co);
    }

    // prologue: stage 0 <- tile 0
    {
        const uint32_t kDst = smem_u32(sK0);
        for (int c = tid; c < 2048; c += 256) {
            int r = c >> 5, co = (c & 31) * 8;
            cpa16(kDst + (r * LDH + co) * 2,             Kb + (size_t)r * 256 + co);
            cpa16(kDst + (TILEH + r * LDH + co) * 2,     Vb + (size_t)r * 256 + co);
        }
        cpa_commit();
    }

    float o[32][4];
    #pragma unroll
    for (int t = 0; t < 32; t++) { o[t][0] = 0; o[t][1] = 0; o[t][2] = 0; o[t][3] = 0; }
    float m0 = -1e30f, m1 = -1e30f, l0 = 0.0f, l1 = 0.0f;

    const uint32_t aBase  = smem_u32(sQ + (warp * 16 + (lane & 15)) * LDH + (lane >> 4) * 8);
    // K (B-operand, non-trans ldsm) lane mapping
    const uint32_t kBase0 = smem_u32(sK0 + ((lane & 7) + ((lane >> 4) & 1) * 8) * LDH + ((lane >> 3) & 1) * 8);
    // V (trans ldsm) lane mapping — distinct from K's
    const uint32_t vBase0 = smem_u32(sV0 + (lane & 15) * LDH + (lane >> 4) * 8);
    const uint32_t kDst0  = smem_u32(sK0);

    for (int ti = 0; ti < SS / 64; ti++) {
        // issue next tile into the other stage
        if (ti + 1 < SS / 64) {
            const uint32_t kDst = kDst0 + ((ti + 1) & 1) * STGH * 2;
            const __half* Kn = Kb + (size_t)(ti + 1) * 64 * 256;
            const __half* Vn = Vb + (size_t)(ti + 1) * 64 * 256;
            for (int c = tid; c < 2048; c += 256) {
                int r = c >> 5, co = (c & 31) * 8;
                cpa16(kDst + (r * LDH + co) * 2,         Kn + (size_t)r * 256 + co);
                cpa16(kDst + (TILEH + r * LDH + co) * 2, Vn + (size_t)r * 256 + co);
            }
        }
        cpa_commit();
        cpa_wait<1>();          // current tile (and Q on ti==0) resident
        __syncthreads();

        const uint32_t kBase = kBase0 + (ti & 1) * STGH * 2;
        const uint32_t vBase = vBase0 + (ti & 1) * STGH * 2;

        // ---- S = Q K^T ----
        float s[8][4];
        #pragma unroll
        for (int j = 0; j < 8; j++) { s[j][0] = 0; s[j][1] = 0; s[j][2] = 0; s[j][3] = 0; }

        #pragma unroll
        for (int kk = 0; kk < 16; kk++) {
            uint32_t a0, a1, a2, a3;
            ldsm4(a0, a1, a2, a3, aBase + kk * 32);
            #pragma unroll
            for (int jj = 0; jj < 4; jj++) {
                uint32_t k0, k1, k2, k3;
                ldsm4(k0, k1, k2, k3, kBase + jj * 16 * LDH * 2 + kk * 32);
                mma16816(s[2 * jj],     a0, a1, a2, a3, k0, k1);
                mma16816(s[2 * jj + 1], a0, a1, a2, a3, k2, k3);
            }
        }

        // ---- online softmax ----
        float rmax0 = -1e30f, rmax1 = -1e30f;
        #pragma unroll
        for (int j = 0; j < 8; j++) {
            rmax0 = fmaxf(rmax0, fmaxf(s[j][0], s[j][1]));
            rmax1 = fmaxf(rmax1, fmaxf(s[j][2], s[j][3]));
        }
        rmax0 = fmaxf(rmax0, __shfl_xor_sync(0xffffffffu, rmax0, 1));
        rmax0 = fmaxf(rmax0, __shfl_xor_sync(0xffffffffu, rmax0, 2));
        rmax1 = fmaxf(rmax1, __shfl_xor_sync(0xffffffffu, rmax1, 1));
        rmax1 = fmaxf(rmax1, __shfl_xor_sync(0xffffffffu, rmax1, 2));

        float mn0 = fmaxf(m0, rmax0), mn1 = fmaxf(m1, rmax1);
        float corr0 = exp2f((m0 - mn0) * L2E);
        float corr1 = exp2f((m1 - mn1) * L2E);
        m0 = mn0; m1 = mn1;

        uint32_t pl[8], ph[8];
        float rs0 = 0.0f, rs1 = 0.0f;
        #pragma unroll
        for (int j = 0; j < 8; j++) {
            float p0 = exp2f((s[j][0] - mn0) * L2E);
            float p1 = exp2f((s[j][1] - mn0) * L2E);
            float p2 = exp2f((s[j][2] - mn1) * L2E);
            float p3 = exp2f((s[j][3] - mn1) * L2E);
            rs0 += p0 + p1; rs1 += p2 + p3;
            pl[j] = packh2(p0, p1);
            ph[j] = packh2(p2, p3);
        }
        rs0 += __shfl_xor_sync(0xffffffffu, rs0, 1);
        rs0 += __shfl_xor_sync(0xffffffffu, rs0, 2);
        rs1 += __shfl_xor_sync(0xffffffffu, rs1, 1);
        rs1 += __shfl_xor_sync(0xffffffffu, rs1, 2);
        l0 = l0 * corr0 + rs0;
        l1 = l1 * corr1 + rs1;

        #pragma unroll
        for (int t = 0; t < 32; t++) {
            o[t][0] *= corr0; o[t][1] *= corr0;
            o[t][2] *= corr1; o[t][3] *= corr1;
        }

        // ---- O += P V ----
        #pragma unroll
        for (int kk2 = 0; kk2 < 4; kk2++) {
            uint32_t a0 = pl[2 * kk2], a1 = ph[2 * kk2];
            uint32_t a2 = pl[2 * kk2 + 1], a3 = ph[2 * kk2 + 1];
            uint32_t vrow = vBase + kk2 * 16 * LDH * 2;
            #pragma unroll
            for (int nj = 0; nj < 16; nj++) {
                uint32_t v0, v1, v2, v3;
                ldsm4t(v0, v1, v2, v3, vrow + nj * 32);
                mma16816(o[2 * nj],     a0, a1, a2, a3, v0, v1);
                mma16816(o[2 * nj + 1], a0, a1, a2, a3, v2, v3);
            }
        }
        __syncthreads();   // free this stage for the prefetch issued next iteration
    }

    // ---- normalize + store ----
    float inv0 = 1.0f / l0, inv1 = 1.0f / l1;
    float* Ob0 = O + ((size_t)b * SS + q0 + warp * 16 + g) * 256;
    float* Ob1 = Ob0 + 8 * 256;
    #pragma unroll
    for (int j = 0; j < 32; j++) {
        int col = j * 8 + qd * 2;
        float2 w0 = { o[j][0] * inv0, o[j][1] * inv0 };
        float2 w1 = { o[j][2] * inv1, o[j][3] * inv1 };
        *(float2*)(Ob0 + col) = w0;
        *(float2*)(Ob1 + col) = w1;
    }
}

// ---------------------------------------------------------------------------
// LayerNorm(X + R) * g + be — one warp per row; optionally emit fp16
// ---------------------------------------------------------------------------
template<bool HALF_OUT>
__global__ __launch_bounds__(256) void ln_k(const float* __restrict__ X,
                                            const float* __restrict__ R,
                                            const float* __restrict__ g,
                                            const float* __restrict__ be,
                                            void* __restrict__ outv) {
    int row  = (blockIdx.x * blockDim.x + threadIdx.x) >> 5;
    int lane = threadIdx.x & 31;
    const float* xr = X + (size_t)row * DD;
    const float* rr = R + (size_t)row * DD;

    float v[8];
    float s = 0.0f;
    #pragma unroll
    for (int t = 0; t < 8; t++) {
        int d = t * 32 + lane;
        v[t] = xr[d] + rr[d];
        s += v[t];
    }
    #pragma unroll
    for (int o = 16; o; o >>= 1) s += __shfl_xor_sync(0xffffffffu, s, o);
    float mu = s * (1.0f / 256.0f);

    float var = 0.0f;
    #pragma unroll
    for (int t = 0; t < 8; t++) { float dv = v[t] - mu; var += dv * dv; }
    #pragma unroll
    for (int o = 16; o; o >>= 1) var += __shfl_xor_sync(0xffffffffu, var, o);
    var *= (1.0f / 256.0f);
    float rstd = rsqrtf(var + 1e-5f);

    #pragma unroll
    for (int t = 0; t < 8; t++) {
        int d = t * 32 + lane;
        float w = (v[t] - mu) * rstd * g[d] + be[d];
        if (HALF_OUT) ((__half*)outv)[(size_t)row * DD + d] = __float2half_rn(w);
        else          ((float*)outv)[(size_t)row * DD + d] = w;
    }
}

// ---------------------------------------------------------------------------
extern "C" void kernel_launch(void* const* d_in, const int* in_sizes, int n_in,
                              void* d_out, int out_size) {
    (void)in_sizes; (void)n_in; (void)out_size;
    const float* x  = (const float*)d_in[0];
    const float* Wq = (const float*)d_in[1];
    const float* bq = (const float*)d_in[2];
    const float* Wk = (const float*)d_in[3];
    const float* bk = (const float*)d_in[4];
    const float* Wv = (const float*)d_in[5];
    const float* bv = (const float*)d_in[6];
    const float* Wl = (const float*)d_in[7];
    const float* bl = (const float*)d_in[8];
    const float* g1 = (const float*)d_in[9];
    const float* be1= (const float*)d_in[10];
    const float* g2 = (const float*)d_in[11];
    const float* be2= (const float*)d_in[12];
    float* out = (float*)d_out;

    __half *gq, *gk, *gv, *ghh, *gth;
    float *gao, *gt2;
    cudaGetSymbolAddress((void**)&gq,  g_qh);
    cudaGetSymbolAddress((void**)&gk,  g_kh);
    cudaGetSymbolAddress((void**)&gv,  g_vh);
    cudaGetSymbolAddress((void**)&gao, g_ao);
    cudaGetSymbolAddress((void**)&ghh, g_hh);
    cudaGetSymbolAddress((void**)&gth, g_th);
    cudaGetSymbolAddress((void**)&gt2, g_t2);

    cudaFuncSetAttribute(flash_h, cudaFuncAttributeMaxDynamicSharedMemorySize, FLASH_SMEM);

    dim3 ggrid(DD / 128, ROWS / 128);   // (2, 128)

    hgemm_k<float, false, true ><<<ggrid, 256>>>(x, Wq, bq, gq, 0.0625f);
    hgemm_k<float, false, true ><<<ggrid, 256>>>(x, Wk, bk, gk, 1.0f);
    hgemm_k<float, false, true ><<<ggrid, 256>>>(x, Wv, bv, gv, 1.0f);

    flash_h<<<dim3(SS / BRQ, BB), 256, FLASH_SMEM>>>(gq, gk, gv, gao);

    ln_k<true ><<<ROWS / 8, 256>>>(x, gao, g1, be1, ghh);

    hgemm_k<__half, true,  true ><<<ggrid, 256>>>(ghh, Wl, bl, gth, 1.0f);
    hgemm_k<__half, false, false><<<ggrid, 256>>>(gth, Wl, bl, gt2, 1.0f);

    ln_k<false><<<ROWS / 8, 256>>>(x, gt2, g2, be2, out);
}